// round 1
// baseline (speedup 1.0000x reference)
#include <cuda_runtime.h>
#include <math.h>
#include <stdint.h>

// Problem constants
#define BV    64
#define SV    512
#define DIMV  1024
#define COVV  256
#define ROWS  (BV*SV)        // 32768
#define G3    768            // 3*COV
#define XW    2049           // 2*DIM+1 (w_ih row stride)

// ---------------- scratch (device globals; no runtime allocation) ----------
__device__ float g_ctx[(size_t)ROWS * DIMV];      // 128 MB
__device__ float g_gx [(size_t)ROWS * G3];        // 96 MB
__device__ float g_gh [(size_t)ROWS * G3];        // 96 MB
__device__ float g_target[BV * DIMV];
__device__ float g_hB[BV * G3];
__device__ float g_score_part[8 * ROWS];          // 8 column-tile partials
__device__ float g_attn[ROWS];
__device__ float g_wc_part[8 * BV * DIMV];        // 8 s-chunk partials
__device__ int   g_maskmode;                      // 0=int32, 1=float32, 2=uint8

// ---------------- mask dtype detection -------------------------------------
// Reads only the first 32 KB (safe for uint8 / int32 / float32 layouts).
__global__ void detect_mask_kernel(const unsigned int* m) {
    __shared__ int notint, notfloat;
    if (threadIdx.x == 0) { notint = 0; notfloat = 0; }
    __syncthreads();
    int li = 0, lf = 0;
    for (int i = threadIdx.x; i < 8192; i += 256) {
        unsigned v = m[i];
        if (v > 1u) li = 1;
        if (v != 0u && v != 0x3F800000u) lf = 1;
    }
    if (li) notint = 1;
    if (lf) notfloat = 1;
    __syncthreads();
    if (threadIdx.x == 0) g_maskmode = (!notint) ? 0 : ((!notfloat) ? 1 : 2);
}

// ---------------- shared SGEMM mainloop: C[128,128] += A[M,K] * B[N,K]^T ----
// 256 threads, 8x8 microtile per thread, BK=8. B loads scalar (ldb may be odd).
__device__ __forceinline__ void gemm_main(
    const float* __restrict__ A, int lda,
    const float* __restrict__ B, int ldb, int K,
    int row0, int col0,
    float (&As)[8][128], float (&Bs)[8][128], float (&acc)[8][8])
{
    const int tid = threadIdx.x;
    const int ar  = tid >> 1;
    const int ak  = (tid & 1) * 4;
    const int tr  = tid >> 4;
    const int tc  = tid & 15;

    for (int kt = 0; kt < K; kt += 8) {
        const float* Ap = A + (size_t)(row0 + ar) * lda + kt + ak;
        float4 av = *(const float4*)Ap;
        As[ak + 0][ar] = av.x; As[ak + 1][ar] = av.y;
        As[ak + 2][ar] = av.z; As[ak + 3][ar] = av.w;

        const float* Bp = B + (size_t)(col0 + ar) * ldb + kt + ak;
        Bs[ak + 0][ar] = Bp[0]; Bs[ak + 1][ar] = Bp[1];
        Bs[ak + 2][ar] = Bp[2]; Bs[ak + 3][ar] = Bp[3];
        __syncthreads();

        #pragma unroll
        for (int k = 0; k < 8; ++k) {
            float4 a0 = *(const float4*)&As[k][tr * 8];
            float4 a1 = *(const float4*)&As[k][tr * 8 + 4];
            float4 b0 = *(const float4*)&Bs[k][tc * 8];
            float4 b1 = *(const float4*)&Bs[k][tc * 8 + 4];
            float a[8] = {a0.x, a0.y, a0.z, a0.w, a1.x, a1.y, a1.z, a1.w};
            float b[8] = {b0.x, b0.y, b0.z, b0.w, b1.x, b1.y, b1.z, b1.w};
            #pragma unroll
            for (int i = 0; i < 8; ++i)
                #pragma unroll
                for (int j = 0; j < 8; ++j)
                    acc[i][j] += a[i] * b[j];
        }
        __syncthreads();
    }
}

// ---------------- target = h@W_in^T, hB = h@w_ih[:,1024:2048]^T -------------
__global__ void target_kernel(const float* __restrict__ h,
                              const float* __restrict__ W_in,
                              const float* __restrict__ w_ih)
{
    __shared__ float hs[DIMV];
    const int b = blockIdx.x, tid = threadIdx.x;
    for (int i = tid; i < DIMV; i += 256) hs[i] = h[b * DIMV + i];
    __syncthreads();

    for (int j = tid; j < DIMV; j += 256) {
        const float4* w = (const float4*)(W_in + (size_t)j * DIMV);
        float acc = 0.f;
        #pragma unroll 4
        for (int k = 0; k < DIMV / 4; ++k) {
            float4 wv = w[k];
            acc += hs[k*4]*wv.x + hs[k*4+1]*wv.y + hs[k*4+2]*wv.z + hs[k*4+3]*wv.w;
        }
        g_target[b * DIMV + j] = acc;
    }
    for (int j = tid; j < G3; j += 256) {
        const float* w = w_ih + (size_t)j * XW + DIMV;  // odd stride: scalar
        float acc = 0.f;
        #pragma unroll 8
        for (int k = 0; k < DIMV; ++k) acc += hs[k] * w[k];
        g_hB[b * G3 + j] = acc;
    }
}

// ---------------- ctx GEMM + fused attention score partials -----------------
// ctx = context + cov @ W_cov^T + b_cov ; score_part[bx] = sum_cols ctx*target
__global__ void ctx_kernel(const float* __restrict__ cov,
                           const float* __restrict__ W_cov,
                           const float* __restrict__ context,
                           const float* __restrict__ b_cov)
{
    __shared__ float As[8][128], Bs[8][128];
    __shared__ float s_part[128][16];
    float acc[8][8] = {};
    const int row0 = blockIdx.y * 128, col0 = blockIdx.x * 128;
    gemm_main(cov, COVV, W_cov, COVV, COVV, row0, col0, As, Bs, acc);

    const int tid = threadIdx.x, tr = tid >> 4, tc = tid & 15;
    #pragma unroll
    for (int i = 0; i < 8; ++i) {
        const int row = row0 + tr * 8 + i;
        const int b = row >> 9;
        const float* tgt = g_target + b * DIMV;
        float ps = 0.f;
        #pragma unroll
        for (int j = 0; j < 8; ++j) {
            const int col = col0 + tc * 8 + j;
            float v = acc[i][j] + context[(size_t)row * DIMV + col] + b_cov[col];
            g_ctx[(size_t)row * DIMV + col] = v;
            ps += v * tgt[col];
        }
        s_part[tr * 8 + i][tc] = ps;
    }
    __syncthreads();
    if (tid < 128) {
        float s = 0.f;
        #pragma unroll
        for (int t = 0; t < 16; ++t) s += s_part[tid][t];
        g_score_part[blockIdx.x * ROWS + row0 + tid] = s;
    }
}

// ---------------- masked softmax over S ------------------------------------
__global__ void softmax_kernel(const void* __restrict__ mask,
                               float* __restrict__ out_attn)
{
    const int b = blockIdx.x, s = threadIdx.x;     // 512 threads
    const int idx = b * SV + s;
    __shared__ float red[SV];

    const int mode = g_maskmode;
    bool masked;
    if (mode == 0)      masked = ((const int*)mask)[idx] != 0;
    else if (mode == 1) masked = ((const float*)mask)[idx] != 0.0f;
    else                masked = ((const unsigned char*)mask)[idx] != 0;

    float sc = 0.f;
    #pragma unroll
    for (int p = 0; p < 8; ++p) sc += g_score_part[p * ROWS + idx];
    if (masked) sc = -INFINITY;

    red[s] = sc; __syncthreads();
    for (int o = 256; o > 0; o >>= 1) {
        if (s < o) red[s] = fmaxf(red[s], red[s + o]);
        __syncthreads();
    }
    const float m = red[0]; __syncthreads();

    const float e = masked ? 0.f : __expf(sc - m);
    red[s] = e; __syncthreads();
    for (int o = 256; o > 0; o >>= 1) {
        if (s < o) red[s] += red[s + o];
        __syncthreads();
    }
    const float a = e / red[0];
    g_attn[idx] = a;
    out_attn[idx] = a;
}

// ---------------- wc partials: wc[b,d] = sum_s attn*ctx ---------------------
__global__ void wc_kernel()
{
    const int b = blockIdx.x, z = blockIdx.y, d = threadIdx.x;  // 1024 threads
    __shared__ float at[64];
    if (d < 64) at[d] = g_attn[b * SV + z * 64 + d];
    __syncthreads();
    float acc = 0.f;
    const float* cp = g_ctx + ((size_t)b * SV + z * 64) * DIMV + d;
    #pragma unroll 8
    for (int s = 0; s < 64; ++s) acc += at[s] * cp[(size_t)s * DIMV];
    g_wc_part[(size_t)z * BV * DIMV + b * DIMV + d] = acc;
}

// ---------------- h_tilde = tanh([wc,h] @ W_out^T) -> out[0:65536] ----------
__global__ void htilde_kernel(const float* __restrict__ h,
                              const float* __restrict__ W_out,
                              float* __restrict__ out)
{
    const int b = blockIdx.x, tid = threadIdx.x;   // 256 threads
    __shared__ float cat[2 * DIMV];
    for (int i = tid; i < DIMV; i += 256) {
        float s = 0.f;
        #pragma unroll
        for (int z = 0; z < 8; ++z) s += g_wc_part[(size_t)z * BV * DIMV + b * DIMV + i];
        cat[i] = s;
        cat[DIMV + i] = h[b * DIMV + i];
    }
    __syncthreads();
    for (int j = tid; j < DIMV; j += 256) {
        const float4* w = (const float4*)(W_out + (size_t)j * 2 * DIMV);
        float acc = 0.f;
        #pragma unroll 4
        for (int k = 0; k < 2 * DIMV / 4; ++k) {
            float4 wv = w[k];
            acc += cat[k*4]*wv.x + cat[k*4+1]*wv.y + cat[k*4+2]*wv.z + cat[k*4+3]*wv.w;
        }
        out[b * DIMV + j] = tanhf(acc);
    }
}

// ---------------- gx = ctx @ w_ih[:, :1024]^T + hB[b] + attn*v + b_ih -------
__global__ void gx_kernel(const float* __restrict__ w_ih,
                          const float* __restrict__ b_ih)
{
    __shared__ float As[8][128], Bs[8][128];
    float acc[8][8] = {};
    const int row0 = blockIdx.y * 128, col0 = blockIdx.x * 128;
    gemm_main((const float*)g_ctx, DIMV, w_ih, XW, DIMV, row0, col0, As, Bs, acc);

    const int tid = threadIdx.x, tr = tid >> 4, tc = tid & 15;
    #pragma unroll
    for (int i = 0; i < 8; ++i) {
        const int row = row0 + tr * 8 + i;
        const int b = row >> 9;
        const float at = g_attn[row];
        #pragma unroll
        for (int j = 0; j < 8; ++j) {
            const int col = col0 + tc * 8 + j;
            float v = acc[i][j] + g_hB[b * G3 + col]
                    + at * w_ih[(size_t)col * XW + 2 * DIMV] + b_ih[col];
            g_gx[(size_t)row * G3 + col] = v;
        }
    }
}

// ---------------- gh = cov @ w_hh^T + b_hh ----------------------------------
__global__ void gh_kernel(const float* __restrict__ cov,
                          const float* __restrict__ w_hh,
                          const float* __restrict__ b_hh)
{
    __shared__ float As[8][128], Bs[8][128];
    float acc[8][8] = {};
    const int row0 = blockIdx.y * 128, col0 = blockIdx.x * 128;
    gemm_main(cov, COVV, w_hh, COVV, COVV, row0, col0, As, Bs, acc);

    const int tid = threadIdx.x, tr = tid >> 4, tc = tid & 15;
    #pragma unroll
    for (int i = 0; i < 8; ++i) {
        const int row = row0 + tr * 8 + i;
        #pragma unroll
        for (int j = 0; j < 8; ++j) {
            const int col = col0 + tc * 8 + j;
            g_gh[(size_t)row * G3 + col] = acc[i][j] + b_hh[col];
        }
    }
}

// ---------------- GRU elementwise -> out[98304:] ----------------------------
__global__ void gru_kernel(const float* __restrict__ cov,
                           float* __restrict__ out_cov)
{
    const size_t idx = (size_t)blockIdx.x * 256 + threadIdx.x;
    const size_t row = idx >> 8;
    const int c = (int)(idx & 255);
    const float* gx = g_gx + row * G3;
    const float* gh = g_gh + row * G3;
    const float r = 1.f / (1.f + __expf(-(gx[c]       + gh[c])));
    const float z = 1.f / (1.f + __expf(-(gx[256 + c] + gh[256 + c])));
    const float n = tanhf(gx[512 + c] + r * gh[512 + c]);
    const float h0 = cov[idx];
    out_cov[idx] = (1.f - z) * n + z * h0;
}

// ---------------- launch ----------------------------------------------------
extern "C" void kernel_launch(void* const* d_in, const int* in_sizes, int n_in,
                              void* d_out, int out_size)
{
    const float* h       = (const float*)d_in[0];
    const float* context = (const float*)d_in[1];
    const float* cov     = (const float*)d_in[2];
    const float* W_in    = (const float*)d_in[3];
    const float* W_out   = (const float*)d_in[4];
    const float* W_cov   = (const float*)d_in[5];
    const float* b_cov   = (const float*)d_in[6];
    const float* w_ih    = (const float*)d_in[7];
    const float* w_hh    = (const float*)d_in[8];
    const float* b_ih    = (const float*)d_in[9];
    const float* b_hh    = (const float*)d_in[10];
    const void*  mask    = d_in[11];

    float* out = (float*)d_out;
    float* out_htilde = out;                       // [64*1024]
    float* out_attn   = out + BV * DIMV;           // [64*512]
    float* out_cov    = out + BV * DIMV + ROWS;    // [64*512*256]

    detect_mask_kernel<<<1, 256>>>((const unsigned int*)mask);
    target_kernel<<<BV, 256>>>(h, W_in, w_ih);
    ctx_kernel<<<dim3(DIMV / 128, ROWS / 128), 256>>>(cov, W_cov, context, b_cov);
    gh_kernel<<<dim3(G3 / 128, ROWS / 128), 256>>>(cov, w_hh, b_hh);
    softmax_kernel<<<BV, SV>>>(mask, out_attn);
    wc_kernel<<<dim3(BV, 8), DIMV>>>();
    htilde_kernel<<<BV, 256>>>(h, W_out, out_htilde);
    gx_kernel<<<dim3(G3 / 128, ROWS / 128), 256>>>(w_ih, b_ih);
    gru_kernel<<<ROWS, 256>>>(cov, out_cov);
}